// round 15
// baseline (speedup 1.0000x reference)
#include <cuda_runtime.h>
#include <cstdint>

#define NN 65536
#define NE 1048576
#define F 128

// ---------------- scratch (static device globals; no allocation) ----------------
__device__ float g_bufA[NN * F];
__device__ float g_bufB[NN * F];
__device__ int   g_deg_out[NN];
__device__ int   g_deg_in[NN];
__device__ int   g_cursor[NN];
__device__ int   g_row_ptr[NN + 1];
__device__ int   g_csr_src[NE];
__device__ float g_csr_w[NE];
__device__ float g_out_norm[NN];
__device__ float g_in_norm[NN];
__device__ int   g_blocksum[64];
__device__ int   g_blockoff[64];

__device__ __forceinline__ uint32_t f2tf32(float f) {
    uint32_t r;
    asm("cvt.rna.tf32.f32 %0, %1;" : "=r"(r) : "f"(f));
    return r;
}

// ---------------- graph preprocessing ----------------
__global__ void k_zero() {
    int i = blockIdx.x * blockDim.x + threadIdx.x;
    if (i < NN) { g_deg_out[i] = 0; g_deg_in[i] = 0; }
}

__global__ void k_hist(const int* __restrict__ src, const int* __restrict__ dst) {
    int i = blockIdx.x * blockDim.x + threadIdx.x;
    if (i < NE) {
        atomicAdd(&g_deg_out[src[i]], 1);
        atomicAdd(&g_deg_in[dst[i]], 1);
    }
}

__global__ void k_norm_out() {
    int i = blockIdx.x * blockDim.x + threadIdx.x;
    if (i < NN) g_out_norm[i] = rsqrtf((float)max(g_deg_out[i], 1));
}

// hierarchical exclusive scan of g_deg_in -> g_row_ptr; also emits in_norm
__global__ __launch_bounds__(1024) void k_scan1() {
    int i = blockIdx.x * 1024 + threadIdx.x;
    int lane = threadIdx.x & 31;
    int w    = threadIdx.x >> 5;
    int d = g_deg_in[i];
    g_in_norm[i] = rsqrtf((float)max(d, 1));
    int v = d;
#pragma unroll
    for (int off = 1; off < 32; off <<= 1) {
        int t = __shfl_up_sync(0xFFFFFFFFu, v, off);
        if (lane >= off) v += t;
    }
    __shared__ int ws[32];
    if (lane == 31) ws[w] = v;
    __syncthreads();
    if (w == 0) {
        int s = ws[lane];
#pragma unroll
        for (int off = 1; off < 32; off <<= 1) {
            int t = __shfl_up_sync(0xFFFFFFFFu, s, off);
            if (lane >= off) s += t;
        }
        ws[lane] = s;
    }
    __syncthreads();
    int warp_off = (w > 0) ? ws[w - 1] : 0;
    g_row_ptr[i] = v - d + warp_off;
    if (threadIdx.x == 1023) g_blocksum[blockIdx.x] = ws[31];
}

__global__ void k_scan2() {
    int t = threadIdx.x;
    int lane = t & 31;
    int w    = t >> 5;
    int d = g_blocksum[t];
    int v = d;
#pragma unroll
    for (int off = 1; off < 32; off <<= 1) {
        int x = __shfl_up_sync(0xFFFFFFFFu, v, off);
        if (lane >= off) v += x;
    }
    __shared__ int s0;
    if (t == 31) s0 = v;
    __syncthreads();
    g_blockoff[t] = v - d + (w ? s0 : 0);
}

__global__ __launch_bounds__(1024) void k_scan3() {
    int i = blockIdx.x * 1024 + threadIdx.x;
    int v = g_row_ptr[i] + g_blockoff[blockIdx.x];
    g_row_ptr[i] = v;
    g_cursor[i]  = v;   // fill's running write position
    if (i == 0) g_row_ptr[NN] = NE;
}

__global__ void k_fill(const int* __restrict__ src, const int* __restrict__ dst,
                       const float* __restrict__ ew) {
    int i = blockIdx.x * blockDim.x + threadIdx.x;
    if (i < NE) {
        int p = atomicAdd(&g_cursor[dst[i]], 1);
        g_csr_src[p] = src[i];
        g_csr_w[p]   = ew[i];
    }
}

// ---------------- TF32 mma.sync GEMM: C = (diag(scale)*A) @ W ----------------
// CTA tile 128(M) x 128(N), K in two 64-chunks through the same smem.
// smem = A[128][68] + B[64][136] = 69.6KB -> 2 CTAs/SM (16 warps).
// 8 warps 4m x 2n; warp tile 32x64 = 2x8 m16n8k8 frags (LDS/MMA = 1.5).
// A bank: 4*grp+tig distinct; B bank: 8*tig+grp distinct.
#define SA_STRIDE 68
#define SB_STRIDE 136
#define SM_B_OFF (128 * SA_STRIDE)           // in floats
#define SMEM_MMA ((128 * SA_STRIDE + 64 * SB_STRIDE) * 4)

__global__ __launch_bounds__(256, 2) void k_gemm_mma(const float* __restrict__ A,
                                                     const float* __restrict__ W,
                                                     const float* __restrict__ scale,
                                                     float* __restrict__ C) {
    extern __shared__ uint32_t sm[];
    uint32_t* sA = sm;
    uint32_t* sB = sm + SM_B_OFF;
    int tid  = threadIdx.x;
    int wid  = tid >> 5;
    int lane = tid & 31;
    int base = blockIdx.x * 128;

    int grp = lane >> 2, tig = lane & 3;
    int wr = (wid & 3) * 32;           // warp m-base (0/32/64/96)
    int wc = (wid >> 2) * 64;          // warp n-base (0/64)

    float c[2][8][4];
#pragma unroll
    for (int mt = 0; mt < 2; mt++)
#pragma unroll
        for (int nt = 0; nt < 8; nt++)
#pragma unroll
            for (int j = 0; j < 4; j++) c[mt][nt][j] = 0.f;

#pragma unroll
    for (int kc = 0; kc < 2; kc++) {
        if (kc) __syncthreads();   // protect smem reuse across chunks

        // fill A chunk (128 rows x 64 k), row-scaled tf32: 2048 float4s
#pragma unroll
        for (int it = 0; it < 8; it++) {
            int idx = it * 256 + tid;
            int row = idx >> 4, c4 = (idx & 15) << 2;
            float sc = scale[base + row];
            float4 a = *(const float4*)&A[(base + row) * F + kc * 64 + c4];
            uint4 t;
            t.x = f2tf32(a.x * sc); t.y = f2tf32(a.y * sc);
            t.z = f2tf32(a.z * sc); t.w = f2tf32(a.w * sc);
            *(uint4*)&sA[row * SA_STRIDE + c4] = t;
        }
        // fill B chunk (64 k-rows x 128 n): 2048 float4s
#pragma unroll
        for (int it = 0; it < 8; it++) {
            int idx = it * 256 + tid;
            int k = idx >> 5, c4 = (idx & 31) << 2;
            float4 b = *(const float4*)&W[(kc * 64 + k) * F + c4];
            uint4 u;
            u.x = f2tf32(b.x); u.y = f2tf32(b.y);
            u.z = f2tf32(b.z); u.w = f2tf32(b.w);
            *(uint4*)&sB[k * SB_STRIDE + c4] = u;
        }
        __syncthreads();

#pragma unroll
        for (int k8 = 0; k8 < 64; k8 += 8) {
            uint32_t af[2][4];
#pragma unroll
            for (int mt = 0; mt < 2; mt++) {
                int r0 = wr + mt * 16 + grp;
                af[mt][0] = sA[r0 * SA_STRIDE + k8 + tig];
                af[mt][1] = sA[(r0 + 8) * SA_STRIDE + k8 + tig];
                af[mt][2] = sA[r0 * SA_STRIDE + k8 + tig + 4];
                af[mt][3] = sA[(r0 + 8) * SA_STRIDE + k8 + tig + 4];
            }
            uint32_t bf[8][2];
#pragma unroll
            for (int nt = 0; nt < 8; nt++) {
                int nb = wc + nt * 8 + grp;
                bf[nt][0] = sB[(k8 + tig) * SB_STRIDE + nb];
                bf[nt][1] = sB[(k8 + tig + 4) * SB_STRIDE + nb];
            }
#pragma unroll
            for (int mt = 0; mt < 2; mt++)
#pragma unroll
                for (int nt = 0; nt < 8; nt++) {
                    asm volatile(
                        "mma.sync.aligned.m16n8k8.row.col.f32.tf32.tf32.f32 "
                        "{%0,%1,%2,%3}, {%4,%5,%6,%7}, {%8,%9}, {%0,%1,%2,%3};"
                        : "+f"(c[mt][nt][0]), "+f"(c[mt][nt][1]),
                          "+f"(c[mt][nt][2]), "+f"(c[mt][nt][3])
                        : "r"(af[mt][0]), "r"(af[mt][1]), "r"(af[mt][2]), "r"(af[mt][3]),
                          "r"(bf[nt][0]), "r"(bf[nt][1]));
                }
        }
    }

#pragma unroll
    for (int mt = 0; mt < 2; mt++) {
        int r0 = base + wr + mt * 16 + grp;
#pragma unroll
        for (int nt = 0; nt < 8; nt++) {
            int cb = wc + nt * 8 + tig * 2;
            *(float2*)&C[r0 * F + cb]       = make_float2(c[mt][nt][0], c[mt][nt][1]);
            *(float2*)&C[(r0 + 8) * F + cb] = make_float2(c[mt][nt][2], c[mt][nt][3]);
        }
    }
}

// ---------------- CSR aggregation: one warp per dst node ----------------
template <int MODE>
__global__ __launch_bounds__(256) void k_agg(const float* __restrict__ H,
                                             const float* __restrict__ bias,
                                             float* __restrict__ out) {
    int gw   = (blockIdx.x * blockDim.x + threadIdx.x) >> 5;
    int lane = threadIdx.x & 31;
    int wl   = threadIdx.x >> 5;
    __shared__ int   sh_idx[8][32];
    __shared__ float sh_w[8][32];
    if (gw >= NN) return;

    int beg = g_row_ptr[gw];
    int end = g_row_ptr[gw + 1];
    float4 acc = make_float4(0.f, 0.f, 0.f, 0.f);

    for (int e = beg; e < end;) {
        int n = min(32, end - e);
        sh_idx[wl][lane] = (lane < n) ? g_csr_src[e + lane] : 0;
        if (MODE == 2) sh_w[wl][lane] = (lane < n) ? g_csr_w[e + lane] : 0.f;
        __syncwarp();
#pragma unroll 8
        for (int j = 0; j < n; j++) {
            int s = sh_idx[wl][j];
            float4 x = *(const float4*)&H[s * F + lane * 4];
            if (MODE == 2) {
                float w = sh_w[wl][j];
                acc.x += w * x.x; acc.y += w * x.y;
                acc.z += w * x.z; acc.w += w * x.w;
            } else {
                acc.x += x.x; acc.y += x.y; acc.z += x.z; acc.w += x.w;
            }
        }
        __syncwarp();
        e += n;
    }

    if (MODE != 2) {
        float nrm = g_in_norm[gw];
        float4 b  = *(const float4*)&bias[lane * 4];
        acc.x = acc.x * nrm + b.x;
        acc.y = acc.y * nrm + b.y;
        acc.z = acc.z * nrm + b.z;
        acc.w = acc.w * nrm + b.w;
        if (MODE == 0) {
            acc.x = fmaxf(acc.x, 0.f); acc.y = fmaxf(acc.y, 0.f);
            acc.z = fmaxf(acc.z, 0.f); acc.w = fmaxf(acc.w, 0.f);
        }
    }
    *(float4*)&out[gw * F + lane * 4] = acc;
}

// ---------------- launch ----------------
extern "C" void kernel_launch(void* const* d_in, const int* in_sizes, int n_in,
                              void* d_out, int out_size) {
    const float* feat = (const float*)d_in[0];
    const float* ew   = (const float*)d_in[1];
    const float* W1   = (const float*)d_in[2];
    const float* b1   = (const float*)d_in[3];
    const float* W2   = (const float*)d_in[4];
    const float* b2   = (const float*)d_in[5];
    const int*   src  = (const int*)d_in[6];
    const int*   dst  = (const int*)d_in[7];
    float* out = (float*)d_out;

    float *pA, *pB, *pOutNorm;
    cudaGetSymbolAddress((void**)&pA, g_bufA);
    cudaGetSymbolAddress((void**)&pB, g_bufB);
    cudaGetSymbolAddress((void**)&pOutNorm, g_out_norm);

    static bool attr_done = false;
    if (!attr_done) {
        cudaFuncSetAttribute(k_gemm_mma, cudaFuncAttributeMaxDynamicSharedMemorySize, SMEM_MMA);
        attr_done = true;
    }

    // serial, single stream. GEMM1 placed 4th so ncu's sample window lands on it.
    k_zero<<<NN / 256, 256>>>();
    k_hist<<<NE / 256, 256>>>(src, dst);
    k_norm_out<<<NN / 256, 256>>>();
    k_gemm_mma<<<NN / 128, 256, SMEM_MMA>>>(feat, W1, pOutNorm, pA);  // layer-1 GEMM

    k_scan1<<<64, 1024>>>();      // also computes in_norm
    k_scan2<<<1, 64>>>();
    k_scan3<<<64, 1024>>>();      // also seeds cursor
    k_fill<<<NE / 256, 256>>>(src, dst, ew);

    k_agg<0><<<(NN * 32) / 256, 256>>>(pA, b1, pB);
    k_gemm_mma<<<NN / 128, 256, SMEM_MMA>>>(pB, W2, pOutNorm, pA);
    k_agg<1><<<(NN * 32) / 256, 256>>>(pA, b2, pB);
    k_agg<2><<<(NN * 32) / 256, 256>>>(pB, nullptr, out);
}

// round 16
// speedup vs baseline: 1.0306x; 1.0306x over previous
#include <cuda_runtime.h>
#include <cstdint>

#define NN 65536
#define NE 1048576
#define F 128

// ---------------- scratch (static device globals; no allocation) ----------------
__device__ float  g_bufA[NN * F];
__device__ float  g_bufB[NN * F];
__device__ int    g_deg_out[NN];
__device__ int    g_deg_in[NN];
__device__ int    g_cursor[NN];
__device__ int    g_row_ptr[NN + 1];
__device__ float2 g_csr_ew[NE];      // .x = __int_as_float(src), .y = eweight
__device__ float  g_in_norm[NN];
__device__ int    g_blocksum[64];
__device__ int    g_blockoff[64];

__device__ __forceinline__ uint32_t f2tf32(float f) {
    uint32_t r;
    asm("cvt.rna.tf32.f32 %0, %1;" : "=r"(r) : "f"(f));
    return r;
}

// ---------------- graph preprocessing ----------------
__global__ void k_zero() {
    int i = blockIdx.x * blockDim.x + threadIdx.x;
    if (i < NN) { g_deg_out[i] = 0; g_deg_in[i] = 0; }
}

__global__ void k_hist(const int* __restrict__ src, const int* __restrict__ dst) {
    int i = blockIdx.x * blockDim.x + threadIdx.x;
    if (i < NE) {
        atomicAdd(&g_deg_out[src[i]], 1);
        atomicAdd(&g_deg_in[dst[i]], 1);
    }
}

// hierarchical exclusive scan of g_deg_in -> g_row_ptr; also emits in_norm
__global__ __launch_bounds__(1024) void k_scan1() {
    int i = blockIdx.x * 1024 + threadIdx.x;
    int lane = threadIdx.x & 31;
    int w    = threadIdx.x >> 5;
    int d = g_deg_in[i];
    g_in_norm[i] = rsqrtf((float)max(d, 1));
    int v = d;
#pragma unroll
    for (int off = 1; off < 32; off <<= 1) {
        int t = __shfl_up_sync(0xFFFFFFFFu, v, off);
        if (lane >= off) v += t;
    }
    __shared__ int ws[32];
    if (lane == 31) ws[w] = v;
    __syncthreads();
    if (w == 0) {
        int s = ws[lane];
#pragma unroll
        for (int off = 1; off < 32; off <<= 1) {
            int t = __shfl_up_sync(0xFFFFFFFFu, s, off);
            if (lane >= off) s += t;
        }
        ws[lane] = s;
    }
    __syncthreads();
    int warp_off = (w > 0) ? ws[w - 1] : 0;
    g_row_ptr[i] = v - d + warp_off;
    if (threadIdx.x == 1023) g_blocksum[blockIdx.x] = ws[31];
}

__global__ void k_scan2() {
    int t = threadIdx.x;
    int lane = t & 31;
    int w    = t >> 5;
    int d = g_blocksum[t];
    int v = d;
#pragma unroll
    for (int off = 1; off < 32; off <<= 1) {
        int x = __shfl_up_sync(0xFFFFFFFFu, v, off);
        if (lane >= off) v += x;
    }
    __shared__ int s0;
    if (t == 31) s0 = v;
    __syncthreads();
    g_blockoff[t] = v - d + (w ? s0 : 0);
}

__global__ __launch_bounds__(1024) void k_scan3() {
    int i = blockIdx.x * 1024 + threadIdx.x;
    int v = g_row_ptr[i] + g_blockoff[blockIdx.x];
    g_row_ptr[i] = v;
    g_cursor[i]  = v;   // fill's running write position
    if (i == 0) g_row_ptr[NN] = NE;
}

__global__ void k_fill(const int* __restrict__ src, const int* __restrict__ dst,
                       const float* __restrict__ ew) {
    int i = blockIdx.x * blockDim.x + threadIdx.x;
    if (i < NE) {
        int p = atomicAdd(&g_cursor[dst[i]], 1);
        g_csr_ew[p] = make_float2(__int_as_float(src[i]), ew[i]);  // one 8B scatter
    }
}

// ---------------- TF32 mma.sync GEMM: C = (diag(rsqrt(deg))*A) @ W ----------------
// Round-13 config (best measured): CTA 128(M) x 64(N), grid (NN/128) x 2.
// smem = A[128][132] + B[128][72] = 104.5KB -> 2 CTAs/SM.
// 8 warps 4m x 2n; warp tile 32x32 = 2x4 m16n8k8 frags (LDS/MMA = 2.0).
// A bank: 4*grp+tig distinct; B bank: 8*tig+grp distinct.
#define SA_STRIDE 132
#define SB_STRIDE 72
#define SM_B_OFF (128 * SA_STRIDE)           // in floats
#define SMEM_MMA ((128 * SA_STRIDE + 128 * SB_STRIDE) * 4)

__global__ __launch_bounds__(256, 2) void k_gemm_mma(const float* __restrict__ A,
                                                     const float* __restrict__ W,
                                                     const int* __restrict__ deg,
                                                     float* __restrict__ C) {
    extern __shared__ uint32_t sm[];
    uint32_t* sA = sm;
    uint32_t* sB = sm + SM_B_OFF;
    int tid  = threadIdx.x;
    int wid  = tid >> 5;
    int lane = tid & 31;
    int bm = blockIdx.x >> 1;          // m-tile
    int bn = blockIdx.x & 1;           // n-half
    int base = bm * 128;
    int ncol = bn * 64;

    // fill A (128x128, row-scaled tf32): 4096 float4s -> 16 iters of 256
#pragma unroll
    for (int it = 0; it < 16; it++) {
        int idx = it * 256 + tid;
        int row = idx >> 5, c4 = (idx & 31) << 2;
        float sc = rsqrtf((float)max(deg[base + row], 1));   // fused out_norm
        float4 a = *(const float4*)&A[(base + row) * F + c4];
        uint4 t;
        t.x = f2tf32(a.x * sc); t.y = f2tf32(a.y * sc);
        t.z = f2tf32(a.z * sc); t.w = f2tf32(a.w * sc);
        *(uint4*)&sA[row * SA_STRIDE + c4] = t;
    }
    // fill B (128 x 64 half of W): 2048 float4s -> 8 iters of 256
#pragma unroll
    for (int it = 0; it < 8; it++) {
        int idx = it * 256 + tid;
        int k = idx >> 4, c4 = (idx & 15) << 2;
        float4 b = *(const float4*)&W[k * F + ncol + c4];
        uint4 u;
        u.x = f2tf32(b.x); u.y = f2tf32(b.y);
        u.z = f2tf32(b.z); u.w = f2tf32(b.w);
        *(uint4*)&sB[k * SB_STRIDE + c4] = u;
    }
    __syncthreads();

    int grp = lane >> 2, tig = lane & 3;
    int wr = (wid & 3) * 32;           // warp m-base (0/32/64/96)
    int wc = (wid >> 2) * 32;          // warp n-base (0/32)

    float c[2][4][4];
#pragma unroll
    for (int mt = 0; mt < 2; mt++)
#pragma unroll
        for (int nt = 0; nt < 4; nt++)
#pragma unroll
            for (int j = 0; j < 4; j++) c[mt][nt][j] = 0.f;

#pragma unroll
    for (int k8 = 0; k8 < 128; k8 += 8) {
        uint32_t af[2][4];
#pragma unroll
        for (int mt = 0; mt < 2; mt++) {
            int r0 = wr + mt * 16 + grp;
            af[mt][0] = sA[r0 * SA_STRIDE + k8 + tig];
            af[mt][1] = sA[(r0 + 8) * SA_STRIDE + k8 + tig];
            af[mt][2] = sA[r0 * SA_STRIDE + k8 + tig + 4];
            af[mt][3] = sA[(r0 + 8) * SA_STRIDE + k8 + tig + 4];
        }
        uint32_t bf[4][2];
#pragma unroll
        for (int nt = 0; nt < 4; nt++) {
            int nb = wc + nt * 8 + grp;
            bf[nt][0] = sB[(k8 + tig) * SB_STRIDE + nb];
            bf[nt][1] = sB[(k8 + tig + 4) * SB_STRIDE + nb];
        }
#pragma unroll
        for (int mt = 0; mt < 2; mt++)
#pragma unroll
            for (int nt = 0; nt < 4; nt++) {
                asm volatile(
                    "mma.sync.aligned.m16n8k8.row.col.f32.tf32.tf32.f32 "
                    "{%0,%1,%2,%3}, {%4,%5,%6,%7}, {%8,%9}, {%0,%1,%2,%3};"
                    : "+f"(c[mt][nt][0]), "+f"(c[mt][nt][1]),
                      "+f"(c[mt][nt][2]), "+f"(c[mt][nt][3])
                    : "r"(af[mt][0]), "r"(af[mt][1]), "r"(af[mt][2]), "r"(af[mt][3]),
                      "r"(bf[nt][0]), "r"(bf[nt][1]));
            }
    }

#pragma unroll
    for (int mt = 0; mt < 2; mt++) {
        int r0 = base + wr + mt * 16 + grp;
#pragma unroll
        for (int nt = 0; nt < 4; nt++) {
            int cb = ncol + wc + nt * 8 + tig * 2;
            *(float2*)&C[r0 * F + cb]       = make_float2(c[mt][nt][0], c[mt][nt][1]);
            *(float2*)&C[(r0 + 8) * F + cb] = make_float2(c[mt][nt][2], c[mt][nt][3]);
        }
    }
}

// ---------------- CSR aggregation: one warp per dst node ----------------
// MODE 0: out = relu(acc * in_norm + bias)
// MODE 1: out = acc * in_norm + bias
// MODE 2: out = sum(w_e * H[src_e])
template <int MODE>
__global__ __launch_bounds__(256) void k_agg(const float* __restrict__ H,
                                             const float* __restrict__ bias,
                                             float* __restrict__ out) {
    int gw   = (blockIdx.x * blockDim.x + threadIdx.x) >> 5;
    int lane = threadIdx.x & 31;
    int wl   = threadIdx.x >> 5;
    __shared__ int   sh_idx[8][32];
    __shared__ float sh_w[8][32];
    if (gw >= NN) return;

    int beg = g_row_ptr[gw];
    int end = g_row_ptr[gw + 1];
    float4 acc = make_float4(0.f, 0.f, 0.f, 0.f);

    for (int e = beg; e < end;) {
        int n = min(32, end - e);
        float2 p = (lane < n) ? g_csr_ew[e + lane] : make_float2(0.f, 0.f);
        sh_idx[wl][lane] = __float_as_int(p.x);
        if (MODE == 2) sh_w[wl][lane] = p.y;
        __syncwarp();
#pragma unroll 8
        for (int j = 0; j < n; j++) {
            int s = sh_idx[wl][j];
            float4 x = *(const float4*)&H[s * F + lane * 4];
            if (MODE == 2) {
                float w = sh_w[wl][j];
                acc.x += w * x.x; acc.y += w * x.y;
                acc.z += w * x.z; acc.w += w * x.w;
            } else {
                acc.x += x.x; acc.y += x.y; acc.z += x.z; acc.w += x.w;
            }
        }
        __syncwarp();
        e += n;
    }

    if (MODE != 2) {
        float nrm = g_in_norm[gw];
        float4 b  = *(const float4*)&bias[lane * 4];
        acc.x = acc.x * nrm + b.x;
        acc.y = acc.y * nrm + b.y;
        acc.z = acc.z * nrm + b.z;
        acc.w = acc.w * nrm + b.w;
        if (MODE == 0) {
            acc.x = fmaxf(acc.x, 0.f); acc.y = fmaxf(acc.y, 0.f);
            acc.z = fmaxf(acc.z, 0.f); acc.w = fmaxf(acc.w, 0.f);
        }
    }
    *(float4*)&out[gw * F + lane * 4] = acc;
}

// ---------------- launch ----------------
extern "C" void kernel_launch(void* const* d_in, const int* in_sizes, int n_in,
                              void* d_out, int out_size) {
    const float* feat = (const float*)d_in[0];
    const float* ew   = (const float*)d_in[1];
    const float* W1   = (const float*)d_in[2];
    const float* b1   = (const float*)d_in[3];
    const float* W2   = (const float*)d_in[4];
    const float* b2   = (const float*)d_in[5];
    const int*   src  = (const int*)d_in[6];
    const int*   dst  = (const int*)d_in[7];
    float* out = (float*)d_out;

    float *pA, *pB;
    int *pDegOut;
    cudaGetSymbolAddress((void**)&pA, g_bufA);
    cudaGetSymbolAddress((void**)&pB, g_bufB);
    cudaGetSymbolAddress((void**)&pDegOut, g_deg_out);

    static bool attr_done = false;
    if (!attr_done) {
        cudaFuncSetAttribute(k_gemm_mma, cudaFuncAttributeMaxDynamicSharedMemorySize, SMEM_MMA);
        attr_done = true;
    }

    // serial, single stream. GEMM1 is the 4th launch (ncu sample window).
    k_zero<<<NN / 256, 256>>>();
    k_hist<<<NE / 256, 256>>>(src, dst);
    k_scan1<<<64, 1024>>>();      // in_norm + block-local prefix
    k_gemm_mma<<<(NN / 128) * 2, 256, SMEM_MMA>>>(feat, W1, pDegOut, pA);  // layer-1 GEMM

    k_scan2<<<1, 64>>>();
    k_scan3<<<64, 1024>>>();      // finalize row_ptr, seed cursor
    k_fill<<<NE / 256, 256>>>(src, dst, ew);

    k_agg<0><<<(NN * 32) / 256, 256>>>(pA, b1, pB);
    k_gemm_mma<<<(NN / 128) * 2, 256, SMEM_MMA>>>(pB, W2, pDegOut, pA);
    k_agg<1><<<(NN * 32) / 256, 256>>>(pA, b2, pB);
    k_agg<2><<<(NN * 32) / 256, 256>>>(pB, nullptr, out);
}